// round 2
// baseline (speedup 1.0000x reference)
#include <cuda_runtime.h>
#include <cuda_bf16.h>
#include <cstdint>

// ============================================================
// Problem sizes
// ============================================================
#define B_DIM 16384
#define D_DIM 1024
#define E_DIM 512
#define NEXP  12                 // 4 shared + 2*4 task experts
#define NTOT  (NEXP * E_DIM)     // 6144 concatenated expert columns
#define KC3   (3 * D_DIM)        // 3072: [x_hi | x_lo | x_hi] k-concat

// GEMM tiling
#define BM 128
#define BN 128
#define BK 64
#define NCHUNK (KC3 / BK)        // 48
#define STAGES 3
#define STAGE_BYTES (2 * BM * BK * 2)    // A tile + B tile = 32 KB
#define GEMM_SMEM (STAGES * STAGE_BYTES) // 96 KB

// ============================================================
// Device scratch (static: no runtime allocation allowed)
// ============================================================
__device__ __nv_bfloat16 g_ac[(size_t)B_DIM * KC3];   // A' [b][3072]
__device__ __nv_bfloat16 g_wc[(size_t)NTOT * KC3];    // B' [n][3072] (K-major)
__device__ float         g_bcv[NTOT];                 // concatenated biases
__device__ float         g_G[(size_t)B_DIM * 16];     // softmax gates
__device__ float         g_Y[(size_t)B_DIM * NTOT];   // relu(x@W+b) fp32

// ============================================================
// Helpers
// ============================================================
__device__ __forceinline__ uint32_t smem_u32(const void* p) {
    uint32_t a;
    asm("{ .reg .u64 t; cvta.to.shared.u64 t, %1; cvt.u32.u64 %0, t; }"
        : "=r"(a) : "l"(p));
    return a;
}

#define SWZ(off) ((off) ^ (((off) >> 3) & 0x70))

__device__ __forceinline__ void cp_async16(uint32_t saddr, const void* g) {
    asm volatile("cp.async.cg.shared.global [%0], [%1], 16;"
                 :: "r"(saddr), "l"(g));
}
#define CP_COMMIT() asm volatile("cp.async.commit_group;" ::: "memory")
#define CP_WAIT1()  asm volatile("cp.async.wait_group 1;" ::: "memory")

__device__ __forceinline__ void ldsm4(uint32_t& r0, uint32_t& r1, uint32_t& r2,
                                      uint32_t& r3, uint32_t addr) {
    asm volatile("ldmatrix.sync.aligned.m8n8.x4.shared.b16 {%0,%1,%2,%3}, [%4];"
                 : "=r"(r0), "=r"(r1), "=r"(r2), "=r"(r3) : "r"(addr));
}

__device__ __forceinline__ void mma16816(float* c, const uint32_t* a,
                                         uint32_t b0, uint32_t b1) {
    asm volatile(
        "mma.sync.aligned.m16n8k16.row.col.f32.bf16.bf16.f32 "
        "{%0,%1,%2,%3}, {%4,%5,%6,%7}, {%8,%9}, {%0,%1,%2,%3};"
        : "+f"(c[0]), "+f"(c[1]), "+f"(c[2]), "+f"(c[3])
        : "r"(a[0]), "r"(a[1]), "r"(a[2]), "r"(a[3]), "r"(b0), "r"(b1));
}

__device__ __forceinline__ void split_bf16(float v, __nv_bfloat16& h, __nv_bfloat16& l) {
    h = __float2bfloat16(v);
    l = __float2bfloat16(v - __bfloat162float(h));
}

// ============================================================
// Kernel 1: x -> A' = [x_hi | x_lo | x_hi] per row
// ============================================================
__global__ void convert_x_kernel(const float* __restrict__ x) {
    const int n4 = (B_DIM * D_DIM) >> 2;
    for (int i = blockIdx.x * blockDim.x + threadIdx.x; i < n4;
         i += gridDim.x * blockDim.x) {
        float4 v = reinterpret_cast<const float4*>(x)[i];
        __nv_bfloat16 h0, h1, h2, h3, l0, l1, l2, l3;
        split_bf16(v.x, h0, l0);
        split_bf16(v.y, h1, l1);
        split_bf16(v.z, h2, l2);
        split_bf16(v.w, h3, l3);
        const int b = i >> 8;              // D/4 = 256 float4 per row
        const int k = (i & 255) << 2;
        __nv_bfloat162 hi01 = __halves2bfloat162(h0, h1);
        __nv_bfloat162 hi23 = __halves2bfloat162(h2, h3);
        __nv_bfloat162 lo01 = __halves2bfloat162(l0, l1);
        __nv_bfloat162 lo23 = __halves2bfloat162(l2, l3);
        __nv_bfloat162* dst = reinterpret_cast<__nv_bfloat162*>(
            g_ac + (size_t)b * KC3 + k);
        dst[0] = hi01; dst[1] = hi23;                       // seg0: x_hi
        dst[512] = lo01; dst[513] = lo23;                   // seg1: x_lo (+1024)
        dst[1024] = hi01; dst[1025] = hi23;                 // seg2: x_hi (+2048)
    }
}

// ============================================================
// Kernel 2: weights -> B' rows [n][3072] = [w_hi | w_hi | w_lo], transposed.
// Ws[e][d][n] / Wt[t][k][d][n] -> g_wc[(e*512+n)][k-major]
// ============================================================
__global__ void convert_w_kernel(const float* __restrict__ Ws,
                                 const float* __restrict__ Wt) {
    __shared__ float s[32][33];
    const int e_idx = blockIdx.z;
    const int k0 = blockIdx.x * 32;
    const int n0 = blockIdx.y * 32;
    const int tx = threadIdx.x, ty = threadIdx.y;

    const float* src = (e_idx < 4)
        ? (Ws + (size_t)e_idx * D_DIM * E_DIM)
        : (Wt + (size_t)(e_idx - 4) * D_DIM * E_DIM);

    #pragma unroll
    for (int i = 0; i < 4; ++i) {
        int k = k0 + ty + i * 8;
        s[ty + i * 8][tx] = src[(size_t)k * E_DIM + (n0 + tx)];
    }
    __syncthreads();
    #pragma unroll
    for (int i = 0; i < 4; ++i) {
        int n = n0 + ty + i * 8;
        int k = k0 + tx;
        float v = s[tx][ty + i * 8];
        __nv_bfloat16 h, l;
        split_bf16(v, h, l);
        __nv_bfloat16* dst = g_wc + (size_t)(e_idx * E_DIM + n) * KC3 + k;
        dst[0] = h;            // seg0 pairs x_hi
        dst[D_DIM] = h;        // seg1 pairs x_lo
        dst[2 * D_DIM] = l;    // seg2 pairs x_hi
    }
}

// ============================================================
// Kernel 3: concat biases
// ============================================================
__global__ void bias_kernel(const float* __restrict__ bs, const float* __restrict__ bt) {
    int i = blockIdx.x * blockDim.x + threadIdx.x;
    if (i < NTOT) {
        int e_idx = i >> 9;
        int n = i & 511;
        g_bcv[i] = (e_idx < 4) ? bs[e_idx * E_DIM + n] : bt[(e_idx - 4) * E_DIM + n];
    }
}

// ============================================================
// Kernel 4: gates (softmax over 8 per task), Wg cached in SMEM
// ============================================================
__global__ void gates_kernel(const float* __restrict__ x,
                             const float* __restrict__ Wg,
                             const float* __restrict__ bg) {
    extern __shared__ float sg[];       // 2*1024*8 floats = 64 KB
    __shared__ float sbg[16];
    for (int i = threadIdx.x; i < 2 * D_DIM * 8; i += blockDim.x) sg[i] = Wg[i];
    if (threadIdx.x < 16) sbg[threadIdx.x] = bg[threadIdx.x];
    __syncthreads();

    const int wid = threadIdx.x >> 5, lid = threadIdx.x & 31;
    const int nwarps = (gridDim.x * blockDim.x) >> 5;
    for (int b = blockIdx.x * (blockDim.x >> 5) + wid; b < B_DIM; b += nwarps) {
        float acc[16];
        #pragma unroll
        for (int g = 0; g < 16; ++g) acc[g] = 0.f;
        const float* xr = x + (size_t)b * D_DIM;
        for (int k = lid; k < D_DIM; k += 32) {
            float xv = xr[k];
            float4 a0 = *reinterpret_cast<const float4*>(sg + (k << 3));
            float4 a1 = *reinterpret_cast<const float4*>(sg + (k << 3) + 4);
            float4 b0 = *reinterpret_cast<const float4*>(sg + 8192 + (k << 3));
            float4 b1 = *reinterpret_cast<const float4*>(sg + 8192 + (k << 3) + 4);
            acc[0]  = fmaf(xv, a0.x, acc[0]);  acc[1]  = fmaf(xv, a0.y, acc[1]);
            acc[2]  = fmaf(xv, a0.z, acc[2]);  acc[3]  = fmaf(xv, a0.w, acc[3]);
            acc[4]  = fmaf(xv, a1.x, acc[4]);  acc[5]  = fmaf(xv, a1.y, acc[5]);
            acc[6]  = fmaf(xv, a1.z, acc[6]);  acc[7]  = fmaf(xv, a1.w, acc[7]);
            acc[8]  = fmaf(xv, b0.x, acc[8]);  acc[9]  = fmaf(xv, b0.y, acc[9]);
            acc[10] = fmaf(xv, b0.z, acc[10]); acc[11] = fmaf(xv, b0.w, acc[11]);
            acc[12] = fmaf(xv, b1.x, acc[12]); acc[13] = fmaf(xv, b1.y, acc[13]);
            acc[14] = fmaf(xv, b1.z, acc[14]); acc[15] = fmaf(xv, b1.w, acc[15]);
        }
        #pragma unroll
        for (int g = 0; g < 16; ++g)
            #pragma unroll
            for (int off = 16; off; off >>= 1)
                acc[g] += __shfl_xor_sync(0xffffffffu, acc[g], off);
        if (lid == 0) {
            #pragma unroll
            for (int t = 0; t < 2; ++t) {
                float z[8], m = -1e30f;
                #pragma unroll
                for (int j = 0; j < 8; ++j) {
                    z[j] = acc[t * 8 + j] + sbg[t * 8 + j];
                    m = fmaxf(m, z[j]);
                }
                float s = 0.f;
                #pragma unroll
                for (int j = 0; j < 8; ++j) { z[j] = expf(z[j] - m); s += z[j]; }
                float inv = 1.f / s;
                #pragma unroll
                for (int j = 0; j < 8; ++j)
                    g_G[(size_t)b * 16 + t * 8 + j] = z[j] * inv;
            }
        }
    }
}

// ============================================================
// Kernel 5: GEMM Y = relu(A' @ B'^T + bias) via mma.sync bf16,
// fp32 accumulate, 3-stage cp.async pipeline.
// ============================================================
__global__ void __launch_bounds__(256, 2) gemm_kernel() {
    extern __shared__ char smem[];
    __shared__ float sbias[BN];
    const uint32_t sb = smem_u32(smem);
    const int tid = threadIdx.x;
    const int wid = tid >> 5;
    const int lane = tid & 31;
    const int wm = wid >> 2;          // 0..1  (64 rows each)
    const int wn = wid & 3;           // 0..3  (32 cols each)
    const int m0 = blockIdx.y * BM;
    const int n0 = blockIdx.x * BN;

    if (tid < BN) sbias[tid] = g_bcv[n0 + tid];

    const __nv_bfloat16* gA = g_ac + (size_t)m0 * KC3;
    const __nv_bfloat16* gB = g_wc + (size_t)n0 * KC3;

    // ---- prefetch one stage: 128 rows x 64 bf16 (8 x 16B per row) for A and B
    auto prefetch = [&](int c, int s) {
        const uint32_t sA = sb + s * STAGE_BYTES;
        const uint32_t sB = sA + BM * BK * 2;
        const int kc = c * BK;
        #pragma unroll
        for (int it = 0; it < 4; ++it) {
            const int idx = it * 256 + tid;       // 0..1023
            const int r = idx >> 3;
            const int j = idx & 7;
            const uint32_t so = SWZ((uint32_t)(r * 128 + j * 16));
            cp_async16(sA + so, gA + (size_t)r * KC3 + kc + j * 8);
            cp_async16(sB + so, gB + (size_t)r * KC3 + kc + j * 8);
        }
    };

    prefetch(0, 0); CP_COMMIT();
    prefetch(1, 1); CP_COMMIT();

    float acc[4][4][4];
    #pragma unroll
    for (int mi = 0; mi < 4; ++mi)
        #pragma unroll
        for (int nj = 0; nj < 4; ++nj)
            #pragma unroll
            for (int q = 0; q < 4; ++q) acc[mi][nj][q] = 0.f;

    for (int c = 0; c < NCHUNK; ++c) {
        CP_WAIT1();
        __syncthreads();
        if (c + 2 < NCHUNK) prefetch(c + 2, (c + 2) % STAGES);
        CP_COMMIT();

        const int s = c % STAGES;
        const uint32_t sA = sb + s * STAGE_BYTES;
        const uint32_t sB = sA + BM * BK * 2;

        #pragma unroll
        for (int kk = 0; kk < 4; ++kk) {          // 4 x k16
            uint32_t a[4][4];
            #pragma unroll
            for (int mi = 0; mi < 4; ++mi) {
                const int row = wm * 64 + mi * 16 + (lane & 15);
                const int col = kk * 16 + (lane >> 4) * 8;
                ldsm4(a[mi][0], a[mi][1], a[mi][2], a[mi][3],
                      sA + SWZ((uint32_t)(row * 128 + col * 2)));
            }
            uint32_t bf[2][4];
            #pragma unroll
            for (int bi = 0; bi < 2; ++bi) {
                const int nrow = wn * 32 + bi * 16 + ((lane & 16) >> 1) + (lane & 7);
                const int col = kk * 16 + (lane & 8);
                ldsm4(bf[bi][0], bf[bi][1], bf[bi][2], bf[bi][3],
                      sB + SWZ((uint32_t)(nrow * 128 + col * 2)));
            }
            #pragma unroll
            for (int mi = 0; mi < 4; ++mi)
                #pragma unroll
                for (int nj = 0; nj < 4; ++nj)
                    mma16816(acc[mi][nj], a[mi],
                             bf[nj >> 1][(nj & 1) * 2],
                             bf[nj >> 1][(nj & 1) * 2 + 1]);
        }
        __syncthreads();
    }

    // ---- epilogue: bias + relu -> g_Y (fp32)
    const int tq = lane >> 2;      // 0..7
    const int tr = lane & 3;       // 0..3
    #pragma unroll
    for (int mi = 0; mi < 4; ++mi) {
        #pragma unroll
        for (int nj = 0; nj < 4; ++nj) {
            const int coll = wn * 32 + nj * 8 + tr * 2;
            const int col = n0 + coll;
            const float b0v = sbias[coll], b1v = sbias[coll + 1];
            const int row0 = m0 + wm * 64 + mi * 16 + tq;
            float2 v0, v1;
            v0.x = fmaxf(acc[mi][nj][0] + b0v, 0.f);
            v0.y = fmaxf(acc[mi][nj][1] + b1v, 0.f);
            v1.x = fmaxf(acc[mi][nj][2] + b0v, 0.f);
            v1.y = fmaxf(acc[mi][nj][3] + b1v, 0.f);
            *reinterpret_cast<float2*>(g_Y + (size_t)row0 * NTOT + col) = v0;
            *reinterpret_cast<float2*>(g_Y + (size_t)(row0 + 8) * NTOT + col) = v1;
        }
    }
}

// ============================================================
// Kernel 6: combine with gates
// ============================================================
__device__ __forceinline__ void fma4(float4& a, float w, float4 y) {
    a.x = fmaf(w, y.x, a.x); a.y = fmaf(w, y.y, a.y);
    a.z = fmaf(w, y.z, a.z); a.w = fmaf(w, y.w, a.w);
}

__global__ void combine_kernel(float* __restrict__ out) {
    const int gid = blockIdx.x * blockDim.x + threadIdx.x;
    if (gid >= B_DIM * (E_DIM / 4)) return;
    const int b = gid >> 7;
    const int e4 = gid & 127;
    const float4* yrow = reinterpret_cast<const float4*>(g_Y + (size_t)b * NTOT);
    const float* g = g_G + (size_t)b * 16;

    float4 a0 = make_float4(0.f, 0.f, 0.f, 0.f);
    float4 a1 = make_float4(0.f, 0.f, 0.f, 0.f);
    #pragma unroll
    for (int k = 0; k < 4; ++k) {                 // shared experts
        float4 y = yrow[k * 128 + e4];
        fma4(a0, g[k], y);
        fma4(a1, g[8 + k], y);
    }
    #pragma unroll
    for (int j = 0; j < 4; ++j) {                 // task-0 experts
        float4 y = yrow[(4 + j) * 128 + e4];
        fma4(a0, g[4 + j], y);
    }
    #pragma unroll
    for (int j = 0; j < 4; ++j) {                 // task-1 experts
        float4 y = yrow[(8 + j) * 128 + e4];
        fma4(a1, g[12 + j], y);
    }
    float4* o = reinterpret_cast<float4*>(out);
    o[(size_t)b * 128 + e4] = a0;
    o[(size_t)(B_DIM + b) * 128 + e4] = a1;
}

// ============================================================
// Launch
// ============================================================
extern "C" void kernel_launch(void* const* d_in, const int* in_sizes, int n_in,
                              void* d_out, int out_size) {
    const float* x  = (const float*)d_in[0];
    const float* Ws = (const float*)d_in[1];
    const float* bs = (const float*)d_in[2];
    const float* Wt = (const float*)d_in[3];
    const float* bt = (const float*)d_in[4];
    const float* Wg = (const float*)d_in[5];
    const float* bg = (const float*)d_in[6];
    float* out = (float*)d_out;

    cudaFuncSetAttribute(gemm_kernel, cudaFuncAttributeMaxDynamicSharedMemorySize,
                         GEMM_SMEM);
    cudaFuncSetAttribute(gates_kernel, cudaFuncAttributeMaxDynamicSharedMemorySize,
                         2 * D_DIM * 8 * (int)sizeof(float));

    convert_x_kernel<<<2048, 256>>>(x);

    dim3 wgrid(D_DIM / 32, E_DIM / 32, NEXP);
    convert_w_kernel<<<wgrid, dim3(32, 8)>>>(Ws, Wt);

    bias_kernel<<<(NTOT + 255) / 256, 256>>>(bs, bt);

    gates_kernel<<<256, 256, 2 * D_DIM * 8 * sizeof(float)>>>(x, Wg, bg);

    gemm_kernel<<<dim3(NTOT / BN, B_DIM / BM), 256, GEMM_SMEM>>>();

    combine_kernel<<<(B_DIM * (E_DIM / 4)) / 256, 256>>>(out);
}

// round 5
// speedup vs baseline: 1.1149x; 1.1149x over previous
#include <cuda_runtime.h>
#include <cuda_bf16.h>
#include <cstdint>

// ============================================================
// Problem sizes
// ============================================================
#define B_DIM 16384
#define D_DIM 1024
#define E_DIM 512
#define NEXP  12                 // 4 shared + 2*4 task experts
#define NTOT  (NEXP * E_DIM)     // 6144 concatenated expert columns
#define KC2   (2 * D_DIM)        // 2048 physical cols: [hi | lo]

// GEMM tiling: logical K = 3072 (hh, lh, hl), physical segments deduped
#define BM 128
#define BN 128
#define BK 64
#define NCHUNK 48                // 3 * 1024 / 64
#define STAGES 3
#define STAGE_BYTES (2 * BM * BK * 2)    // A tile + B tile = 32 KB
#define GEMM_SMEM (STAGES * STAGE_BYTES) // 96 KB

// ============================================================
// Device scratch (static: no runtime allocation allowed)
// ============================================================
__device__ __nv_bfloat16 g_ac[(size_t)B_DIM * KC2];   // A [b][hi(1024)|lo(1024)]
__device__ __nv_bfloat16 g_wc[(size_t)NTOT * KC2];    // B [n][hi|lo] (K-major)
__device__ float         g_bcv[NTOT];                 // concatenated biases
__device__ float         g_G[(size_t)B_DIM * 16];     // softmax gates
__device__ float         g_Y[(size_t)B_DIM * NTOT];   // relu(x@W+b) fp32

// ============================================================
// Helpers
// ============================================================
__device__ __forceinline__ uint32_t smem_u32(const void* p) {
    uint32_t a;
    asm("{ .reg .u64 t; cvta.to.shared.u64 t, %1; cvt.u32.u64 %0, t; }"
        : "=r"(a) : "l"(p));
    return a;
}

#define SWZ(off) ((off) ^ (((off) >> 3) & 0x70))

__device__ __forceinline__ void cp_async16(uint32_t saddr, const void* g) {
    asm volatile("cp.async.cg.shared.global [%0], [%1], 16;"
                 :: "r"(saddr), "l"(g));
}
#define CP_COMMIT() asm volatile("cp.async.commit_group;" ::: "memory")
#define CP_WAIT1()  asm volatile("cp.async.wait_group 1;" ::: "memory")

__device__ __forceinline__ void ldsm4(uint32_t& r0, uint32_t& r1, uint32_t& r2,
                                      uint32_t& r3, uint32_t addr) {
    asm volatile("ldmatrix.sync.aligned.m8n8.x4.shared.b16 {%0,%1,%2,%3}, [%4];"
                 : "=r"(r0), "=r"(r1), "=r"(r2), "=r"(r3) : "r"(addr));
}

__device__ __forceinline__ void mma16816(float* c, const uint32_t* a,
                                         uint32_t b0, uint32_t b1) {
    asm volatile(
        "mma.sync.aligned.m16n8k16.row.col.f32.bf16.bf16.f32 "
        "{%0,%1,%2,%3}, {%4,%5,%6,%7}, {%8,%9}, {%0,%1,%2,%3};"
        : "+f"(c[0]), "+f"(c[1]), "+f"(c[2]), "+f"(c[3])
        : "r"(a[0]), "r"(a[1]), "r"(a[2]), "r"(a[3]), "r"(b0), "r"(b1));
}

__device__ __forceinline__ void split_bf16(float v, __nv_bfloat16& h, __nv_bfloat16& l) {
    h = __float2bfloat16(v);
    l = __float2bfloat16(v - __bfloat162float(h));
}

// ============================================================
// Kernel 1: x -> [x_hi | x_lo] per row (2048 cols)
// ============================================================
__global__ void convert_x_kernel(const float* __restrict__ x) {
    const int n4 = (B_DIM * D_DIM) >> 2;
    for (int i = blockIdx.x * blockDim.x + threadIdx.x; i < n4;
         i += gridDim.x * blockDim.x) {
        float4 v = reinterpret_cast<const float4*>(x)[i];
        __nv_bfloat16 h0, h1, h2, h3, l0, l1, l2, l3;
        split_bf16(v.x, h0, l0);
        split_bf16(v.y, h1, l1);
        split_bf16(v.z, h2, l2);
        split_bf16(v.w, h3, l3);
        const int b = i >> 8;              // D/4 = 256 float4 per row
        const int k = (i & 255) << 2;
        __nv_bfloat162* dst = reinterpret_cast<__nv_bfloat162*>(
            g_ac + (size_t)b * KC2 + k);
        dst[0]   = __halves2bfloat162(h0, h1);
        dst[1]   = __halves2bfloat162(h2, h3);
        dst[512] = __halves2bfloat162(l0, l1);    // +1024 elements
        dst[513] = __halves2bfloat162(l2, l3);
    }
}

// ============================================================
// Kernel 2: weights -> [w_hi | w_lo] rows (K-major, transposed)
// ============================================================
__global__ void convert_w_kernel(const float* __restrict__ Ws,
                                 const float* __restrict__ Wt) {
    __shared__ float s[32][33];
    const int e_idx = blockIdx.z;
    const int k0 = blockIdx.x * 32;
    const int n0 = blockIdx.y * 32;
    const int tx = threadIdx.x, ty = threadIdx.y;

    const float* src = (e_idx < 4)
        ? (Ws + (size_t)e_idx * D_DIM * E_DIM)
        : (Wt + (size_t)(e_idx - 4) * D_DIM * E_DIM);

    #pragma unroll
    for (int i = 0; i < 4; ++i) {
        int k = k0 + ty + i * 8;
        s[ty + i * 8][tx] = src[(size_t)k * E_DIM + (n0 + tx)];
    }
    __syncthreads();
    #pragma unroll
    for (int i = 0; i < 4; ++i) {
        int n = n0 + ty + i * 8;
        int k = k0 + tx;
        float v = s[tx][ty + i * 8];
        __nv_bfloat16 h, l;
        split_bf16(v, h, l);
        __nv_bfloat16* dst = g_wc + (size_t)(e_idx * E_DIM + n) * KC2 + k;
        dst[0] = h;
        dst[D_DIM] = l;
    }
}

// ============================================================
// Kernel 3: concat biases
// ============================================================
__global__ void bias_kernel(const float* __restrict__ bs, const float* __restrict__ bt) {
    int i = blockIdx.x * blockDim.x + threadIdx.x;
    if (i < NTOT) {
        int e_idx = i >> 9;
        int n = i & 511;
        g_bcv[i] = (e_idx < 4) ? bs[e_idx * E_DIM + n] : bt[(e_idx - 4) * E_DIM + n];
    }
}

// ============================================================
// Kernel 4: gates (softmax over 8 per task), Wg cached in SMEM.
// 512 threads x 444 blocks -> 3 CTAs/SM (smem-capped), 75% occ.
// ============================================================
__global__ void gates_kernel(const float* __restrict__ x,
                             const float* __restrict__ Wg,
                             const float* __restrict__ bg) {
    extern __shared__ float sg[];       // 2*1024*8 floats = 64 KB
    __shared__ float sbg[16];
    for (int i = threadIdx.x; i < 2 * D_DIM * 8; i += blockDim.x) sg[i] = Wg[i];
    if (threadIdx.x < 16) sbg[threadIdx.x] = bg[threadIdx.x];
    __syncthreads();

    const int wid = threadIdx.x >> 5, lid = threadIdx.x & 31;
    const int nwarps = (gridDim.x * blockDim.x) >> 5;
    for (int b = blockIdx.x * (blockDim.x >> 5) + wid; b < B_DIM; b += nwarps) {
        float acc[16];
        #pragma unroll
        for (int g = 0; g < 16; ++g) acc[g] = 0.f;
        const float* xr = x + (size_t)b * D_DIM;
        for (int k = lid; k < D_DIM; k += 32) {
            float xv = xr[k];
            float4 a0 = *reinterpret_cast<const float4*>(sg + (k << 3));
            float4 a1 = *reinterpret_cast<const float4*>(sg + (k << 3) + 4);
            float4 b0 = *reinterpret_cast<const float4*>(sg + 8192 + (k << 3));
            float4 b1 = *reinterpret_cast<const float4*>(sg + 8192 + (k << 3) + 4);
            acc[0]  = fmaf(xv, a0.x, acc[0]);  acc[1]  = fmaf(xv, a0.y, acc[1]);
            acc[2]  = fmaf(xv, a0.z, acc[2]);  acc[3]  = fmaf(xv, a0.w, acc[3]);
            acc[4]  = fmaf(xv, a1.x, acc[4]);  acc[5]  = fmaf(xv, a1.y, acc[5]);
            acc[6]  = fmaf(xv, a1.z, acc[6]);  acc[7]  = fmaf(xv, a1.w, acc[7]);
            acc[8]  = fmaf(xv, b0.x, acc[8]);  acc[9]  = fmaf(xv, b0.y, acc[9]);
            acc[10] = fmaf(xv, b0.z, acc[10]); acc[11] = fmaf(xv, b0.w, acc[11]);
            acc[12] = fmaf(xv, b1.x, acc[12]); acc[13] = fmaf(xv, b1.y, acc[13]);
            acc[14] = fmaf(xv, b1.z, acc[14]); acc[15] = fmaf(xv, b1.w, acc[15]);
        }
        #pragma unroll
        for (int g = 0; g < 16; ++g)
            #pragma unroll
            for (int off = 16; off; off >>= 1)
                acc[g] += __shfl_xor_sync(0xffffffffu, acc[g], off);
        if (lid == 0) {
            #pragma unroll
            for (int t = 0; t < 2; ++t) {
                float z[8], m = -1e30f;
                #pragma unroll
                for (int j = 0; j < 8; ++j) {
                    z[j] = acc[t * 8 + j] + sbg[t * 8 + j];
                    m = fmaxf(m, z[j]);
                }
                float s = 0.f;
                #pragma unroll
                for (int j = 0; j < 8; ++j) { z[j] = expf(z[j] - m); s += z[j]; }
                float inv = 1.f / s;
                #pragma unroll
                for (int j = 0; j < 8; ++j)
                    g_G[(size_t)b * 16 + t * 8 + j] = z[j] * inv;
            }
        }
    }
}

// ============================================================
// Kernel 5: GEMM Y = relu(A @ B^T + bias), split-bf16 via 48 logical
// K-chunks mapped onto deduped [hi|lo] storage:
//   c<16:  A hi(c),    B hi(c)      -> x_hi . w_hi
//   16-31: A lo(c-16), B hi(c-16)   -> x_lo . w_hi
//   32-47: A hi(c-32), B lo(c-32)   -> x_hi . w_lo
// 3-stage cp.async pipeline, single syncthreads per chunk.
// ============================================================
__global__ void __launch_bounds__(256, 2) gemm_kernel() {
    extern __shared__ char smem[];
    __shared__ float sbias[BN];
    const uint32_t sb = smem_u32(smem);
    const int tid = threadIdx.x;
    const int wid = tid >> 5;
    const int lane = tid & 31;
    const int wm = wid >> 2;          // 0..1  (64 rows each)
    const int wn = wid & 3;           // 0..3  (32 cols each)
    const int m0 = blockIdx.y * BM;
    const int n0 = blockIdx.x * BN;

    if (tid < BN) sbias[tid] = g_bcv[n0 + tid];

    const __nv_bfloat16* gA = g_ac + (size_t)m0 * KC2;
    const __nv_bfloat16* gB = g_wc + (size_t)n0 * KC2;

    // per-thread gmem/smem offsets for the cooperative stage load
    const int pr = tid >> 3;          // 0..31 base row
    const int pj = tid & 7;           // 16B column within 128B row
    const uint32_t psw = SWZ((uint32_t)(pr * 128 + pj * 16));

    auto prefetch = [&](int c, int s) {
        const int ka = (c < 32 ? c : c - 32) * BK;     // A segment mapping
        const int kb = (c < 16 ? c : c - 16) * BK;     // B segment mapping
        const uint32_t sA = sb + s * STAGE_BYTES;
        const uint32_t sB = sA + BM * BK * 2;
        const __nv_bfloat16* pa = gA + (size_t)pr * KC2 + ka + pj * 8;
        const __nv_bfloat16* pb = gB + (size_t)pr * KC2 + kb + pj * 8;
        #pragma unroll
        for (int it = 0; it < 4; ++it) {
            cp_async16(sA + psw + it * 32 * 128, pa + (size_t)(it * 32) * KC2);
            cp_async16(sB + psw + it * 32 * 128, pb + (size_t)(it * 32) * KC2);
        }
    };

    prefetch(0, 0); CP_COMMIT();
    prefetch(1, 1); CP_COMMIT();

    float acc[4][4][4];
    #pragma unroll
    for (int mi = 0; mi < 4; ++mi)
        #pragma unroll
        for (int nj = 0; nj < 4; ++nj)
            #pragma unroll
            for (int q = 0; q < 4; ++q) acc[mi][nj][q] = 0.f;

    // per-thread unswizzled ldmatrix offsets (stage-base independent:
    // stage stride is 32KB-aligned, swizzle only touches bits [4..9])
    const int arow = wm * 64 + (lane & 15);
    const int acolb = (lane >> 4) * 16;               // bytes
    const int brow = wn * 32 + ((lane & 16) >> 1) + (lane & 7);
    const int bcolb = (lane & 8) * 2;                 // bytes

    for (int c = 0; c < NCHUNK; ++c) {
        CP_WAIT1();
        __syncthreads();
        if (c + 2 < NCHUNK) prefetch(c + 2, (c + 2) % STAGES);
        CP_COMMIT();

        const int s = c % STAGES;
        const uint32_t sA = sb + s * STAGE_BYTES;
        const uint32_t sB = sA + BM * BK * 2;

        #pragma unroll
        for (int kk = 0; kk < 4; ++kk) {          // 4 x k16
            uint32_t a[4][4];
            #pragma unroll
            for (int mi = 0; mi < 4; ++mi) {
                const uint32_t off = (uint32_t)((arow + mi * 16) * 128 + acolb + kk * 32);
                ldsm4(a[mi][0], a[mi][1], a[mi][2], a[mi][3], sA + SWZ(off));
            }
            uint32_t bf[2][4];
            #pragma unroll
            for (int bi = 0; bi < 2; ++bi) {
                const uint32_t off = (uint32_t)((brow + bi * 16) * 128 + bcolb + kk * 32);
                ldsm4(bf[bi][0], bf[bi][1], bf[bi][2], bf[bi][3], sB + SWZ(off));
            }
            #pragma unroll
            for (int mi = 0; mi < 4; ++mi)
                #pragma unroll
                for (int nj = 0; nj < 4; ++nj)
                    mma16816(acc[mi][nj], a[mi],
                             bf[nj >> 1][(nj & 1) * 2],
                             bf[nj >> 1][(nj & 1) * 2 + 1]);
        }
    }

    // ---- epilogue: bias + relu -> g_Y (fp32)
    const int tq = lane >> 2;      // 0..7
    const int tr = lane & 3;       // 0..3
    #pragma unroll
    for (int mi = 0; mi < 4; ++mi) {
        #pragma unroll
        for (int nj = 0; nj < 4; ++nj) {
            const int coll = wn * 32 + nj * 8 + tr * 2;
            const int col = n0 + coll;
            const float b0v = sbias[coll], b1v = sbias[coll + 1];
            const int row0 = m0 + wm * 64 + mi * 16 + tq;
            float2 v0, v1;
            v0.x = fmaxf(acc[mi][nj][0] + b0v, 0.f);
            v0.y = fmaxf(acc[mi][nj][1] + b1v, 0.f);
            v1.x = fmaxf(acc[mi][nj][2] + b0v, 0.f);
            v1.y = fmaxf(acc[mi][nj][3] + b1v, 0.f);
            *reinterpret_cast<float2*>(g_Y + (size_t)row0 * NTOT + col) = v0;
            *reinterpret_cast<float2*>(g_Y + (size_t)(row0 + 8) * NTOT + col) = v1;
        }
    }
}

// ============================================================
// Kernel 6: combine with gates
// ============================================================
__device__ __forceinline__ void fma4(float4& a, float w, float4 y) {
    a.x = fmaf(w, y.x, a.x); a.y = fmaf(w, y.y, a.y);
    a.z = fmaf(w, y.z, a.z); a.w = fmaf(w, y.w, a.w);
}

__global__ void combine_kernel(float* __restrict__ out) {
    const int gid = blockIdx.x * blockDim.x + threadIdx.x;
    if (gid >= B_DIM * (E_DIM / 4)) return;
    const int b = gid >> 7;
    const int e4 = gid & 127;
    const float4* yrow = reinterpret_cast<const float4*>(g_Y + (size_t)b * NTOT);
    const float* g = g_G + (size_t)b * 16;

    float4 a0 = make_float4(0.f, 0.f, 0.f, 0.f);
    float4 a1 = make_float4(0.f, 0.f, 0.f, 0.f);
    #pragma unroll
    for (int k = 0; k < 4; ++k) {                 // shared experts
        float4 y = yrow[k * 128 + e4];
        fma4(a0, g[k], y);
        fma4(a1, g[8 + k], y);
    }
    #pragma unroll
    for (int j = 0; j < 4; ++j) {                 // task-0 experts
        float4 y = yrow[(4 + j) * 128 + e4];
        fma4(a0, g[4 + j], y);
    }
    #pragma unroll
    for (int j = 0; j < 4; ++j) {                 // task-1 experts
        float4 y = yrow[(8 + j) * 128 + e4];
        fma4(a1, g[12 + j], y);
    }
    float4* o = reinterpret_cast<float4*>(out);
    o[(size_t)b * 128 + e4] = a0;
    o[(size_t)(B_DIM + b) * 128 + e4] = a1;
}

// ============================================================
// Launch
// ============================================================
extern "C" void kernel_launch(void* const* d_in, const int* in_sizes, int n_in,
                              void* d_out, int out_size) {
    const float* x  = (const float*)d_in[0];
    const float* Ws = (const float*)d_in[1];
    const float* bs = (const float*)d_in[2];
    const float* Wt = (const float*)d_in[3];
    const float* bt = (const float*)d_in[4];
    const float* Wg = (const float*)d_in[5];
    const float* bg = (const float*)d_in[6];
    float* out = (float*)d_out;

    cudaFuncSetAttribute(gemm_kernel, cudaFuncAttributeMaxDynamicSharedMemorySize,
                         GEMM_SMEM);
    cudaFuncSetAttribute(gates_kernel, cudaFuncAttributeMaxDynamicSharedMemorySize,
                         2 * D_DIM * 8 * (int)sizeof(float));

    convert_x_kernel<<<2048, 256>>>(x);

    dim3 wgrid(D_DIM / 32, E_DIM / 32, NEXP);
    convert_w_kernel<<<wgrid, dim3(32, 8)>>>(Ws, Wt);

    bias_kernel<<<(NTOT + 255) / 256, 256>>>(bs, bt);

    gates_kernel<<<444, 512, 2 * D_DIM * 8 * sizeof(float)>>>(x, Wg, bg);

    gemm_kernel<<<dim3(NTOT / BN, B_DIM / BM), 256, GEMM_SMEM>>>();

    combine_kernel<<<(B_DIM * (E_DIM / 4)) / 256, 256>>>(out);
}